// round 2
// baseline (speedup 1.0000x reference)
#include <cuda_runtime.h>
#include <math.h>

#define N_TIME   8192
#define NBANDS   128
#define THREADS  256
#define CHUNK    32                 // elements per thread
#define NF4      (N_TIME / 4)       // 2048 float4 per row
#define F4PT     (NF4 / THREADS)    // 8 float4 per thread

// MUFU EX2 via inline PTX (the CUDA "__exp2f" intrinsic does not exist;
// exp2f() is the slow accurate path without -use_fast_math).
__device__ __forceinline__ float ex2f(float x) {
    float y;
    asm("ex2.approx.ftz.f32 %0, %1;" : "=f"(y) : "f"(x));
    return y;
}
__device__ __forceinline__ float lg2f(float x) {
    float y;
    asm("lg2.approx.ftz.f32 %0, %1;" : "=f"(y) : "f"(x));
    return y;
}

// XOR swizzle at float4 granularity: avoids bank conflicts for both the
// coalesced (stride-1) pattern and the per-thread-chunk (stride-8) pattern.
__device__ __forceinline__ int swz(int v) { return v ^ ((v >> 3) & 7); }

__global__ void __launch_bounds__(THREADS)
mrpcen_kernel(const float* __restrict__ x,
              const float* __restrict__ log_alpha,
              const float* __restrict__ log_delta,
              const float* __restrict__ log_r,
              float* __restrict__ out,
              float4 sv, int nbands)
{
    __shared__ float4 stage[NF4];     // 32 KB staging (input, then each output row)
    __shared__ float  warp_tot[8];
    __shared__ float  warp_excl[8];

    const int row  = blockIdx.x;              // b*F + f
    const int b    = row / nbands;
    const int f    = row % nbands;
    const int tid  = threadIdx.x;
    const int lane = tid & 31;
    const int warp = tid >> 5;

    const float4* __restrict__ xrow4 =
        reinterpret_cast<const float4*>(x) + (size_t)row * NF4;

    // ---- coalesced load of the full row into swizzled staging ----
    #pragma unroll
    for (int i = 0; i < F4PT; i++) {
        int g = i * THREADS + tid;
        stage[swz(g)] = __ldg(xrow4 + g);
    }

    const float m0    = __ldg(x + (size_t)row * N_TIME);   // m[-1] = x[0]
    const float alpha = ex2f(1.4426950408889634f * __ldg(log_alpha + f));
    const float delta = ex2f(1.4426950408889634f * __ldg(log_delta + f));
    const float rr    = ex2f(1.4426950408889634f * __ldg(log_r + f));
    const float dr    = ex2f(rr * lg2f(delta));            // delta^r

    __syncthreads();

    // ---- gather my contiguous 32-element chunk into registers ----
    float xv[CHUNK];
    #pragma unroll
    for (int i = 0; i < F4PT; i++) {
        float4 v = stage[swz(tid * F4PT + i)];
        xv[4*i+0] = v.x; xv[4*i+1] = v.y; xv[4*i+2] = v.z; xv[4*i+3] = v.w;
    }

    #pragma unroll 1
    for (int tv = 0; tv < 4; tv++) {
        const float s = (tv == 0) ? sv.x : (tv == 1) ? sv.y : (tv == 2) ? sv.z : sv.w;
        const float q = 1.0f - s;
        // Pc = q^CHUNK via exact repeated squaring
        const float q2 = q * q, q4 = q2 * q2, q8 = q4 * q4, q16 = q8 * q8;
        const float Pc = q16 * q16;

        // local affine reduction: chunk with m_in = 0 gives contribution C
        float c = 0.0f;
        #pragma unroll
        for (int i = 0; i < CHUNK; i++) c = fmaf(q, c, s * xv[i]);

        // warp-level inclusive scan:  S_j = C_j + Pc * S_{j-1}
        float S  = c;
        float Pp = Pc;
        #pragma unroll
        for (int o = 1; o < 32; o <<= 1) {
            float v = __shfl_up_sync(0xffffffffu, S, o);
            if (lane >= o) S = fmaf(Pp, v, S);
            Pp *= Pp;                   // after loop: Pp = Pc^32
        }
        if (lane == 31) warp_tot[warp] = S;
        float Sex = __shfl_up_sync(0xffffffffu, S, 1);
        if (lane == 0) Sex = 0.0f;
        __syncthreads();

        // block-level scan of the 8 warp totals (multiplier Pc^32)
        if (warp == 0) {
            float W  = (lane < 8) ? warp_tot[lane] : 0.0f;
            float Pq = Pp;
            #pragma unroll
            for (int o = 1; o < 8; o <<= 1) {
                float v = __shfl_up_sync(0xffffffffu, W, o);
                if (lane >= o) W = fmaf(Pq, v, W);
                Pq *= Pq;
            }
            float Wex = __shfl_up_sync(0xffffffffu, W, 1);
            if (lane == 0) Wex = 0.0f;
            if (lane < 8) warp_excl[lane] = Wex;
        }
        __syncthreads();

        // entering value for my chunk:
        //   m_in = Sex + Pc^lane * Wexcl(warp) + Pc^tid * m0
        const float Wex  = warp_excl[warp];
        const float lPc  = lg2f(Pc);
        const float Pl   = ex2f((float)lane * lPc);
        const float Ptid = ex2f((float)tid  * lPc);
        float carry = fmaf(Pl, Wex, Sex) + Ptid * m0;

        // ---- emit: rerun EMA + PCEN pointwise, write into staging ----
        #pragma unroll
        for (int i = 0; i < F4PT; i++) {
            float4 o4;
            #pragma unroll
            for (int k = 0; k < 4; k++) {
                const float xi = xv[4*i + k];
                carry = fmaf(q, carry, s * xi);
                const float u  = 1e-5f + carry;                    // EPS + m
                const float sm = ex2f(-alpha * lg2f(u));           // (EPS+m)^-a
                const float y  = fmaf(xi, sm, delta);
                const float pc = ex2f(rr * lg2f(y)) - dr;          // y^r - d^r
                (&o4.x)[k] = pc;
            }
            stage[swz(tid * F4PT + i)] = o4;
        }
        __syncthreads();

        // ---- coalesced store of this rate's output row ----
        float4* __restrict__ orow4 = reinterpret_cast<float4*>(out) +
            (((size_t)b * 4 + tv) * nbands + f) * NF4;
        #pragma unroll
        for (int i = 0; i < F4PT; i++) {
            int g = i * THREADS + tid;
            orow4[g] = stage[swz(g)];
        }
        __syncthreads();   // staging reused next iteration
    }
}

extern "C" void kernel_launch(void* const* d_in, const int* in_sizes, int n_in,
                              void* d_out, int out_size)
{
    const float* x  = (const float*)d_in[0];
    const float* la = (const float*)d_in[1];
    const float* ld = (const float*)d_in[2];
    const float* lr = (const float*)d_in[3];
    float* out = (float*)d_out;

    const int nbands = in_sizes[1];                 // 128
    const int rows   = in_sizes[0] / N_TIME;        // B * F = 1024

    // s = (sqrt(1 + 4 t^2) - 1) / (2 t^2), computed in double on host
    const double tvals[4] = {2.0, 8.0, 32.0, 128.0};
    float ss[4];
    for (int i = 0; i < 4; i++) {
        double t = tvals[i];
        ss[i] = (float)((sqrt(1.0 + 4.0 * t * t) - 1.0) / (2.0 * t * t));
    }
    float4 sv = make_float4(ss[0], ss[1], ss[2], ss[3]);

    mrpcen_kernel<<<rows, THREADS>>>(x, la, ld, lr, out, sv, nbands);
}

// round 3
// speedup vs baseline: 1.2412x; 1.2412x over previous
#include <cuda_runtime.h>
#include <math.h>

#define N_TIME   8192
#define NBANDS   128
#define THREADS  256
#define CHUNK    32                 // elements per thread
#define NF4      (N_TIME / 4)       // 2048 float4 per row
#define F4PT     (NF4 / THREADS)    // 8 float4 per thread

// MUFU EX2/LG2 via inline PTX (fast approx path, same units __expf uses).
__device__ __forceinline__ float ex2f(float x) {
    float y;
    asm("ex2.approx.ftz.f32 %0, %1;" : "=f"(y) : "f"(x));
    return y;
}
__device__ __forceinline__ float lg2f(float x) {
    float y;
    asm("lg2.approx.ftz.f32 %0, %1;" : "=f"(y) : "f"(x));
    return y;
}

// XOR swizzle at float4 granularity: conflict-free for both the coalesced
// (stride-1) pattern and the per-thread-chunk (stride-8) pattern.
__device__ __forceinline__ int swz(int v) { return v ^ ((v >> 3) & 7); }

__global__ void __launch_bounds__(THREADS, 3)
mrpcen_kernel(const float* __restrict__ x,
              const float* __restrict__ log_alpha,
              const float* __restrict__ log_delta,
              const float* __restrict__ log_r,
              float* __restrict__ out,
              float4 sv, int nbands)
{
    __shared__ float4 stage[NF4];     // 32 KB staging (input, then each output row)
    __shared__ float  warp_tot[4][8];
    __shared__ float  warp_excl[4][8];

    const int row  = blockIdx.x;              // b*F + f
    const int b    = row / nbands;
    const int f    = row % nbands;
    const int tid  = threadIdx.x;
    const int lane = tid & 31;
    const int warp = tid >> 5;

    const float4* __restrict__ xrow4 =
        reinterpret_cast<const float4*>(x) + (size_t)row * NF4;

    // ---- coalesced load of the full row into swizzled staging ----
    #pragma unroll
    for (int i = 0; i < F4PT; i++) {
        int g = i * THREADS + tid;
        stage[swz(g)] = __ldg(xrow4 + g);
    }

    const float m0    = __ldg(x + (size_t)row * N_TIME);   // m[-1] = x[0]
    const float alpha = ex2f(1.4426950408889634f * __ldg(log_alpha + f));
    const float delta = ex2f(1.4426950408889634f * __ldg(log_delta + f));
    const float rr    = ex2f(1.4426950408889634f * __ldg(log_r + f));
    const float dr    = ex2f(rr * lg2f(delta));            // delta^r

    // per-rate constants
    float s[4], q[4], Pc[4];
    #pragma unroll
    for (int t = 0; t < 4; t++) {
        s[t] = (t == 0) ? sv.x : (t == 1) ? sv.y : (t == 2) ? sv.z : sv.w;
        q[t] = 1.0f - s[t];
        float q2 = q[t] * q[t], q4 = q2 * q2, q8 = q4 * q4, q16 = q8 * q8;
        Pc[t] = q16 * q16;            // q^32 exact (repeated squaring)
    }

    __syncthreads();

    // ---- gather my contiguous 32-element chunk into registers ----
    float xv[CHUNK];
    #pragma unroll
    for (int i = 0; i < F4PT; i++) {
        float4 v = stage[swz(tid * F4PT + i)];
        xv[4*i+0] = v.x; xv[4*i+1] = v.y; xv[4*i+2] = v.z; xv[4*i+3] = v.w;
    }

    // ---- interleaved local affine reduction for all 4 rates ----
    float c[4] = {0.f, 0.f, 0.f, 0.f};
    #pragma unroll
    for (int i = 0; i < CHUNK; i++) {
        const float xi = xv[i];
        #pragma unroll
        for (int t = 0; t < 4; t++) c[t] = fmaf(q[t], c[t], s[t] * xi);
    }

    // ---- interleaved warp-level inclusive scan: S_j = C_j + Pc * S_{j-1} ----
    float S[4], P[4];
    #pragma unroll
    for (int t = 0; t < 4; t++) { S[t] = c[t]; P[t] = Pc[t]; }
    #pragma unroll
    for (int o = 1; o < 32; o <<= 1) {
        #pragma unroll
        for (int t = 0; t < 4; t++) {
            float v = __shfl_up_sync(0xffffffffu, S[t], o);
            if (lane >= o) S[t] = fmaf(P[t], v, S[t]);
            P[t] *= P[t];             // after loop: P[t] = Pc^32
        }
    }
    if (lane == 31) {
        #pragma unroll
        for (int t = 0; t < 4; t++) warp_tot[t][warp] = S[t];
    }
    float Sex[4];
    #pragma unroll
    for (int t = 0; t < 4; t++) {
        Sex[t] = __shfl_up_sync(0xffffffffu, S[t], 1);
        if (lane == 0) Sex[t] = 0.0f;
    }
    __syncthreads();

    // ---- block-level scan of 8 warp totals per rate (multiplier Pc^32) ----
    if (warp == 0) {
        float W[4], Pq[4];
        #pragma unroll
        for (int t = 0; t < 4; t++) {
            W[t]  = (lane < 8) ? warp_tot[t][lane] : 0.0f;
            Pq[t] = P[t];
        }
        #pragma unroll
        for (int o = 1; o < 8; o <<= 1) {
            #pragma unroll
            for (int t = 0; t < 4; t++) {
                float v = __shfl_up_sync(0xffffffffu, W[t], o);
                if (lane >= o) W[t] = fmaf(Pq[t], v, W[t]);
                Pq[t] *= Pq[t];
            }
        }
        #pragma unroll
        for (int t = 0; t < 4; t++) {
            float Wex = __shfl_up_sync(0xffffffffu, W[t], 1);
            if (lane == 0) Wex = 0.0f;
            if (lane < 8) warp_excl[t][lane] = Wex;
        }
    }
    __syncthreads();

    // entering value for my chunk per rate:
    //   m_in = Sex + Pc^lane * Wexcl(warp) + Pc^tid * m0
    float carry[4];
    #pragma unroll
    for (int t = 0; t < 4; t++) {
        const float Wex = warp_excl[t][warp];
        const float lPc = lg2f(Pc[t]);
        carry[t] = fmaf(ex2f((float)lane * lPc), Wex, Sex[t])
                 + ex2f((float)tid * lPc) * m0;
    }

    const float nalpha = -alpha;

    // ---- emit each rate: rerun EMA + PCEN pointwise, stage, store ----
    #pragma unroll
    for (int tv = 0; tv < 4; tv++) {
        const float st = s[tv];
        const float qt = q[tv];
        float cy = carry[tv];

        #pragma unroll
        for (int i = 0; i < F4PT; i++) {
            float4 o4;
            #pragma unroll
            for (int k = 0; k < 4; k++) {
                const float xi = xv[4*i + k];
                cy = fmaf(qt, cy, st * xi);
                const float u  = 1e-5f + cy;                       // EPS + m
                const float sm = ex2f(nalpha * lg2f(u));           // (EPS+m)^-a
                const float y  = fmaf(xi, sm, delta);
                const float pc = ex2f(rr * lg2f(y)) - dr;          // y^r - d^r
                (&o4.x)[k] = pc;
            }
            stage[swz(tid * F4PT + i)] = o4;
        }
        __syncthreads();

        // ---- coalesced store of this rate's output row ----
        float4* __restrict__ orow4 = reinterpret_cast<float4*>(out) +
            (((size_t)b * 4 + tv) * nbands + f) * NF4;
        #pragma unroll
        for (int i = 0; i < F4PT; i++) {
            int g = i * THREADS + tid;
            orow4[g] = stage[swz(g)];
        }
        __syncthreads();   // staging reused next iteration
    }
}

extern "C" void kernel_launch(void* const* d_in, const int* in_sizes, int n_in,
                              void* d_out, int out_size)
{
    const float* x  = (const float*)d_in[0];
    const float* la = (const float*)d_in[1];
    const float* ld = (const float*)d_in[2];
    const float* lr = (const float*)d_in[3];
    float* out = (float*)d_out;

    const int nbands = in_sizes[1];                 // 128
    const int rows   = in_sizes[0] / N_TIME;        // B * F = 1024

    // s = (sqrt(1 + 4 t^2) - 1) / (2 t^2), computed in double on host
    const double tvals[4] = {2.0, 8.0, 32.0, 128.0};
    float ss[4];
    for (int i = 0; i < 4; i++) {
        double t = tvals[i];
        ss[i] = (float)((sqrt(1.0 + 4.0 * t * t) - 1.0) / (2.0 * t * t));
    }
    float4 sv = make_float4(ss[0], ss[1], ss[2], ss[3]);

    mrpcen_kernel<<<rows, THREADS>>>(x, la, ld, lr, out, sv, nbands);
}